// round 14
// baseline (speedup 1.0000x reference)
#include <cuda_runtime.h>
#include <cuda_fp16.h>
#include <mma.h>
#include <math.h>
#include <cstdint>

using namespace nvcuda;

// Problem shapes
#define BATCH 65536
#define DIN   64
#define HID   512

// GEMM tile config (fp16 operands, fp32 accum)
#define BM 128
#define BN 128
#define BKC 64
#define LDA_H 72     // 64 + 8 pad halfs
#define LDB_H 144    // 128 + 16 pad halfs
#define NTHREADS 256
#define STAGES 3

#define A_STAGE_HALFS (BM * LDA_H)     // 9216
#define W_STAGE_HALFS 9216
#define STAGE_HALFS  (A_STAGE_HALFS + W_STAGE_HALFS)   // 18432
#define STAGE_BYTES  (STAGE_HALFS * 2)                 // 36864
#define SMEM_BYTES   (STAGES * STAGE_BYTES)            // 110592 -> 2 CTAs/SM

// ---------------- scratch ----------------
__device__ __align__(256) __half g_xm1[BATCH * DIN];
__device__ __align__(256) __half g_s1[BATCH * HID];
__device__ __align__(256) __half g_s2[BATCH * HID];
__device__ __align__(256) __half g_s3[BATCH * HID];
__device__ __align__(256) __half g_a1[BATCH * HID];
__device__ __align__(256) __half g_a2[BATCH * HID];
__device__ __align__(256) __half g_a3[BATCH * HID];
__device__ __align__(256) __half g_d1[BATCH * HID];
__device__ __align__(256) __half g_d2[BATCH * HID];
__device__ __align__(256) __half g_d3[BATCH * HID];
__device__ __align__(256) __half g_d4[BATCH * HID];
__device__ __align__(256) __half g_wz0[HID * DIN];
__device__ __align__(256) __half g_wz1[HID * HID];
__device__ __align__(256) __half g_wz2[HID * HID];
__device__ __align__(256) __half g_wz3[HID * HID];
__device__ __align__(256) __half g_wx0[HID * DIN];
__device__ __align__(256) __half g_wx1[HID * DIN];
__device__ __align__(256) __half g_wx2[HID * DIN];

// ---------------- prep kernels ----------------
__global__ void sub1_half_kernel(const float* __restrict__ in, __half* __restrict__ out, int n) {
    int i = blockIdx.x * blockDim.x + threadIdx.x;
    if (i < n) out[i] = __float2half_rn(in[i] - 1.0f);
}

__global__ void prep_weights(
    const float* __restrict__ Wz0, const float* __restrict__ Wx0,
    const float* __restrict__ Wx1, const float* __restrict__ Wx2,
    const float* __restrict__ Wz1, const float* __restrict__ Wz2, const float* __restrict__ Wz3,
    __half* __restrict__ wz0, __half* __restrict__ wx0,
    __half* __restrict__ wx1, __half* __restrict__ wx2,
    __half* __restrict__ wz1, __half* __restrict__ wz2, __half* __restrict__ wz3)
{
    const int S = HID * DIN;
    const int L = HID * HID;
    int i = blockIdx.x * blockDim.x + threadIdx.x;
    if (i < 4 * S) {
        int seg = i / S, off = i - seg * S;
        const float* src = (seg == 0) ? Wz0 : (seg == 1) ? Wx0 : (seg == 2) ? Wx1 : Wx2;
        __half* dst      = (seg == 0) ? wz0 : (seg == 1) ? wx0 : (seg == 2) ? wx1 : wx2;
        dst[off] = __float2half_rn(src[off]);
    } else {
        int j = i - 4 * S;
        if (j < 3 * L) {
            int seg = j / L, off = j - seg * L;
            const float* src = (seg == 0) ? Wz1 : (seg == 1) ? Wz2 : Wz3;
            __half* dst      = (seg == 0) ? wz1 : (seg == 1) ? wz2 : wz3;
            dst[off] = __float2half_rn(src[off]);
        }
    }
}

// ---------------- helpers ----------------
__device__ __forceinline__ float softplusf(float p) { return (p > 20.0f) ? p : log1pf(expf(p)); }
__device__ __forceinline__ float sigmoidf_(float p) { return 1.0f / (1.0f + expf(-p)); }

__device__ __forceinline__ void cp16(unsigned int saddr, const __half* g, int bytes) {
    asm volatile("cp.async.cg.shared.global [%0], [%1], 16, %2;\n"
                 :: "r"(saddr), "l"(g), "r"(bytes));
}
__device__ __forceinline__ void cp_commit() { asm volatile("cp.async.commit_group;\n" ::: "memory"); }
__device__ __forceinline__ void cp_wait0() { asm volatile("cp.async.wait_group 0;\n" ::: "memory"); }
__device__ __forceinline__ void cp_wait1() { asm volatile("cp.async.wait_group 1;\n" ::: "memory"); }

// Epilogue modes
#define MODE_FWD 0
#define MODE_L4  1
#define MODE_BWD 2
#define MODE_FIN 3

// ---------------- incremental staging cursor ----------------
struct StageState {
    const __half* A;
    const __half* W;
    int aoff, woff;     // element offsets for slot t=0
    int aT, wT;         // per-slot strides
    int wstep;          // W advance per chunk (A advance is always 64)
    int rem;            // chunks remaining in current segment
    int seg;
};

template<bool BT>
__device__ __forceinline__ void seg_init(StageState& st, const __half* A, const __half* W,
                                         int K, int m0, int n0, int N, int tid)
{
    st.A = A; st.W = W;
    st.rem = K >> 6;
    st.aoff = (m0 + (tid >> 3)) * K + ((tid & 7) << 3);
    st.aT = 32 * K;
    if (BT) {
        st.woff = (n0 + (tid >> 3)) * K + ((tid & 7) << 3);
        st.wT = 32 * K;
        st.wstep = 64;
    } else {
        st.woff = (tid >> 4) * N + n0 + ((tid & 15) << 3);
        st.wT = 16 * N;
        st.wstep = 64 * N;
    }
}

template<bool BT>
__device__ __forceinline__ void do_stage(StageState& st,
    unsigned int sAb, unsigned int sWb, int sA0, int sW0, int wbytes,
    const __half* A1, const __half* W1, int K1,
    const __half* A2, const __half* W2, int K2,
    const __half* A3, const __half* W3, int K3,
    int m0, int n0, int N, int tid)
{
    #pragma unroll
    for (int t = 0; t < 4; t++)
        cp16(sAb + 2 * (sA0 + t * 32 * LDA_H), st.A + st.aoff + t * st.aT, 16);
    if (BT) {
        #pragma unroll
        for (int t = 0; t < 4; t++)
            cp16(sWb + 2 * (sW0 + t * 32 * LDA_H), st.W + st.woff + t * st.wT, 16);
    } else {
        #pragma unroll
        for (int t = 0; t < 4; t++)
            cp16(sWb + 2 * (sW0 + t * 16 * LDB_H), st.W + st.woff + t * st.wT, wbytes);
    }
    st.aoff += 64;
    st.woff += st.wstep;
    if (--st.rem == 0) {
        // advance to next non-empty segment (rare)
        int s = st.seg + 1;
        const __half* A = nullptr; const __half* W = nullptr; int K = 0;
        if (s == 1) { if (K1) { A = A1; W = W1; K = K1; } else s = 2; }
        if (s == 2 && K == 0) { if (K2) { A = A2; W = W2; K = K2; } else s = 3; }
        if (s == 3 && K == 0) { if (K3) { A = A3; W = W3; K = K3; } else s = 4; }
        st.seg = s;
        if (K) seg_init<BT>(st, A, W, K, m0, n0, N, tid);
    }
}

// ---------------- fused fp16 GEMM ----------------
template<bool BT, int MODE>
__global__ void __launch_bounds__(NTHREADS, 2)
gemm_h(const __half* __restrict__ A0, const __half* __restrict__ W0, int K0,
       const __half* __restrict__ A1, const __half* __restrict__ W1, int K1,
       const __half* __restrict__ A2, const __half* __restrict__ W2, int K2,
       const __half* __restrict__ A3, const __half* __restrict__ W3, int K3,
       int N,
       const float* __restrict__ bias,
       const float* __restrict__ vecn,
       const __half* __restrict__ sgate,
       __half* __restrict__ out1h,
       __half* __restrict__ out2h,
       float* __restrict__ out1f)
{
    extern __shared__ __half smem_h[];
    const unsigned int smem_u = (unsigned int)__cvta_generic_to_shared(smem_h);

    const int tid    = threadIdx.x;
    const int warpId = tid >> 5;
    const int lane   = tid & 31;
    const int wm     = warpId >> 2;   // 0..1
    const int wn     = warpId & 3;    // 0..3
    const int m0     = blockIdx.y * BM;
    const int n0     = blockIdx.x * BN;

    // fixed per-thread smem staging offsets (halfs)
    const int sA0 = (tid >> 3) * LDA_H + ((tid & 7) << 3);
    const int sW0 = BT ? sA0 : ((tid >> 4) * LDB_H + ((tid & 15) << 3));
    const int wbytes = BT ? 16 : ((n0 + ((tid & 15) << 3)) < N ? 16 : 0);

    wmma::fragment<wmma::accumulator, 16, 16, 16, float> acc[4][2];
    #pragma unroll
    for (int i = 0; i < 4; i++)
        #pragma unroll
        for (int j = 0; j < 2; j++)
            wmma::fill_fragment(acc[i][j], 0.0f);

    const int niter = (K0 >> 6) + (K1 >> 6) + (K2 >> 6) + (K3 >> 6);

    StageState st;
    st.seg = 0;
    seg_init<BT>(st, A0, W0, K0, m0, n0, N, tid);

    // prologue: stage chunks 0 and 1
    #pragma unroll
    for (int j = 0; j < 2; j++) {
        if (j < niter) {
            unsigned int b = smem_u + j * STAGE_BYTES;
            do_stage<BT>(st, b, b + A_STAGE_HALFS * 2, sA0, sW0, wbytes,
                         A1, W1, K1, A2, W2, K2, A3, W3, K3, m0, n0, N, tid);
            cp_commit();
        }
    }

    int cbuf = 0;                           // compute ring position
    int sbuf = (niter >= 3) ? 2 : 0;        // staging ring position (for chunk it+2)

    for (int it = 0; it < niter; ++it) {
        if (it + 1 < niter) cp_wait1(); else cp_wait0();
        __syncthreads();

        if (it + 2 < niter) {
            unsigned int b = smem_u + sbuf * STAGE_BYTES;
            do_stage<BT>(st, b, b + A_STAGE_HALFS * 2, sA0, sW0, wbytes,
                         A1, W1, K1, A2, W2, K2, A3, W3, K3, m0, n0, N, tid);
            cp_commit();
            sbuf = (sbuf == 2) ? 0 : sbuf + 1;
        }

        __half* sA = smem_h + cbuf * STAGE_HALFS;
        __half* sW = sA + A_STAGE_HALFS;
        cbuf = (cbuf == 2) ? 0 : cbuf + 1;

        #pragma unroll
        for (int kk = 0; kk < BKC; kk += 16) {
            wmma::fragment<wmma::matrix_a, 16, 16, 16, __half, wmma::row_major> af[4];
            #pragma unroll
            for (int i = 0; i < 4; i++)
                wmma::load_matrix_sync(af[i], &sA[(wm * 64 + i * 16) * LDA_H + kk], LDA_H);
            if (BT) {
                wmma::fragment<wmma::matrix_b, 16, 16, 16, __half, wmma::col_major> bf[2];
                #pragma unroll
                for (int j = 0; j < 2; j++)
                    wmma::load_matrix_sync(bf[j], &sW[(wn * 32 + j * 16) * LDA_H + kk], LDA_H);
                #pragma unroll
                for (int i = 0; i < 4; i++)
                    #pragma unroll
                    for (int j = 0; j < 2; j++)
                        wmma::mma_sync(acc[i][j], af[i], bf[j], acc[i][j]);
            } else {
                wmma::fragment<wmma::matrix_b, 16, 16, 16, __half, wmma::row_major> bf[2];
                #pragma unroll
                for (int j = 0; j < 2; j++)
                    wmma::load_matrix_sync(bf[j], &sW[kk * LDB_H + wn * 32 + j * 16], LDB_H);
                #pragma unroll
                for (int i = 0; i < 4; i++)
                    #pragma unroll
                    for (int j = 0; j < 2; j++)
                        wmma::mma_sync(acc[i][j], af[i], bf[j], acc[i][j]);
            }
        }
    }

    // ---- vectorized epilogue ----
    __syncthreads();
    float* ep = reinterpret_cast<float*>(smem_h) + warpId * 288;
    const int er  = lane >> 1;          // 0..15: row within fragment
    const int ech = (lane & 1) << 3;    // 0 or 8: col-half within fragment

    #pragma unroll
    for (int i = 0; i < 4; i++) {
        #pragma unroll
        for (int j = 0; j < 2; j++) {
            const int rbase = m0 + wm * 64 + i * 16;
            const int cbase = n0 + wn * 32 + j * 16;
            if (MODE == MODE_FIN && cbase >= N) continue;   // uniform per warp

            wmma::store_matrix_sync(ep, acc[i][j], 16, wmma::mem_row_major);
            __syncwarp();

            float v[8];
            *reinterpret_cast<float4*>(&v[0]) = *reinterpret_cast<const float4*>(&ep[er * 16 + ech]);
            *reinterpret_cast<float4*>(&v[4]) = *reinterpret_cast<const float4*>(&ep[er * 16 + ech + 4]);
            const int row  = rbase + er;
            const int col0 = cbase + ech;
            const size_t oi = (size_t)row * N + col0;

            if (MODE == MODE_FWD || MODE == MODE_L4) {
                float b[8];
                *reinterpret_cast<float4*>(&b[0]) = *reinterpret_cast<const float4*>(&bias[col0]);
                *reinterpret_cast<float4*>(&b[4]) = *reinterpret_cast<const float4*>(&bias[col0 + 4]);
                if (MODE == MODE_FWD) {
                    union { uint4 u; __half2 h[4]; } o1, o2;
                    #pragma unroll
                    for (int k = 0; k < 4; k++) {
                        float p0 = v[2*k]   + b[2*k];
                        float p1 = v[2*k+1] + b[2*k+1];
                        o1.h[k] = __floats2half2_rn(sigmoidf_(p0), sigmoidf_(p1));
                        o2.h[k] = __floats2half2_rn(softplusf(p0), softplusf(p1));
                    }
                    *reinterpret_cast<uint4*>(&out1h[oi]) = o1.u;
                    *reinterpret_cast<uint4*>(&out2h[oi]) = o2.u;
                } else {
                    float vn[8];
                    *reinterpret_cast<float4*>(&vn[0]) = *reinterpret_cast<const float4*>(&vecn[col0]);
                    *reinterpret_cast<float4*>(&vn[4]) = *reinterpret_cast<const float4*>(&vecn[col0 + 4]);
                    union { uint4 u; __half2 h[4]; } o1;
                    #pragma unroll
                    for (int k = 0; k < 4; k++) {
                        float p0 = v[2*k]   + b[2*k];
                        float p1 = v[2*k+1] + b[2*k+1];
                        o1.h[k] = __floats2half2_rn(vn[2*k] * sigmoidf_(p0), vn[2*k+1] * sigmoidf_(p1));
                    }
                    *reinterpret_cast<uint4*>(&out1h[oi]) = o1.u;
                }
            } else if (MODE == MODE_BWD) {
                union { uint4 u; __half2 h[4]; } g, o;
                g.u = *reinterpret_cast<const uint4*>(&sgate[oi]);
                #pragma unroll
                for (int k = 0; k < 4; k++) {
                    float2 gf = __half22float2(g.h[k]);
                    o.h[k] = __floats2half2_rn(gf.x * v[2*k], gf.y * v[2*k+1]);
                }
                *reinterpret_cast<uint4*>(&out1h[oi]) = o.u;
            } else { // MODE_FIN
                float vn[8];
                *reinterpret_cast<float4*>(&vn[0]) = *reinterpret_cast<const float4*>(&vecn[col0]);
                *reinterpret_cast<float4*>(&vn[4]) = *reinterpret_cast<const float4*>(&vecn[col0 + 4]);
                float4 o0, o1;
                o0.x = v[0] + vn[0]; o0.y = v[1] + vn[1]; o0.z = v[2] + vn[2]; o0.w = v[3] + vn[3];
                o1.x = v[4] + vn[4]; o1.y = v[5] + vn[5]; o1.z = v[6] + vn[6]; o1.w = v[7] + vn[7];
                *reinterpret_cast<float4*>(&out1f[oi])     = o0;
                *reinterpret_cast<float4*>(&out1f[oi + 4]) = o1;
            }
            __syncwarp();
        }
    }
}

// ---------------- host launcher ----------------
extern "C" void kernel_launch(void* const* d_in, const int* in_sizes, int n_in,
                              void* d_out, int out_size)
{
    const float* state = (const float*)d_in[0];
    const float* Wz0   = (const float*)d_in[1];
    const float* bz0   = (const float*)d_in[2];
    const float* Wz1   = (const float*)d_in[3];
    const float* Wz2   = (const float*)d_in[4];
    const float* Wz3   = (const float*)d_in[5];
    const float* WzL   = (const float*)d_in[6];
    const float* Wx0   = (const float*)d_in[7];
    const float* bx0   = (const float*)d_in[8];
    const float* Wx1   = (const float*)d_in[9];
    const float* bx1   = (const float*)d_in[10];
    const float* Wx2   = (const float*)d_in[11];
    const float* bx2   = (const float*)d_in[12];
    const float* WxL   = (const float*)d_in[13];
    float* out = (float*)d_out;

    cudaFuncSetAttribute(gemm_h<true,  MODE_FWD>, cudaFuncAttributeMaxDynamicSharedMemorySize, SMEM_BYTES);
    cudaFuncSetAttribute(gemm_h<true,  MODE_L4>,  cudaFuncAttributeMaxDynamicSharedMemorySize, SMEM_BYTES);
    cudaFuncSetAttribute(gemm_h<false, MODE_BWD>, cudaFuncAttributeMaxDynamicSharedMemorySize, SMEM_BYTES);
    cudaFuncSetAttribute(gemm_h<false, MODE_FIN>, cudaFuncAttributeMaxDynamicSharedMemorySize, SMEM_BYTES);

    void* p;
    __half *xm1, *s1, *s2, *s3, *a1, *a2, *a3, *d1, *d2, *d3, *d4;
    __half *wz0, *wz1, *wz2, *wz3, *wx0, *wx1, *wx2;
    cudaGetSymbolAddress(&p, g_xm1);  xm1  = (__half*)p;
    cudaGetSymbolAddress(&p, g_s1);   s1   = (__half*)p;
    cudaGetSymbolAddress(&p, g_s2);   s2   = (__half*)p;
    cudaGetSymbolAddress(&p, g_s3);   s3   = (__half*)p;
    cudaGetSymbolAddress(&p, g_a1);   a1   = (__half*)p;
    cudaGetSymbolAddress(&p, g_a2);   a2   = (__half*)p;
    cudaGetSymbolAddress(&p, g_a3);   a3   = (__half*)p;
    cudaGetSymbolAddress(&p, g_d1);   d1   = (__half*)p;
    cudaGetSymbolAddress(&p, g_d2);   d2   = (__half*)p;
    cudaGetSymbolAddress(&p, g_d3);   d3   = (__half*)p;
    cudaGetSymbolAddress(&p, g_d4);   d4   = (__half*)p;
    cudaGetSymbolAddress(&p, g_wz0);  wz0  = (__half*)p;
    cudaGetSymbolAddress(&p, g_wz1);  wz1  = (__half*)p;
    cudaGetSymbolAddress(&p, g_wz2);  wz2  = (__half*)p;
    cudaGetSymbolAddress(&p, g_wz3);  wz3  = (__half*)p;
    cudaGetSymbolAddress(&p, g_wx0);  wx0  = (__half*)p;
    cudaGetSymbolAddress(&p, g_wx1);  wx1  = (__half*)p;
    cudaGetSymbolAddress(&p, g_wx2);  wx2  = (__half*)p;

    const int nX = BATCH * DIN;
    sub1_half_kernel<<<(nX + 255) / 256, 256>>>(state, xm1, nX);

    const int nW = 4 * HID * DIN + 3 * HID * HID;
    prep_weights<<<(nW + 255) / 256, 256>>>(Wz0, Wx0, Wx1, Wx2, Wz1, Wz2, Wz3,
                                            wz0, wx0, wx1, wx2, wz1, wz2, wz3);

    dim3 blk(NTHREADS);
    dim3 gH(HID / BN, BATCH / BM);   // (4, 512)
    dim3 gF(1, BATCH / BM);          // (1, 512)

    // Forward (BT=true: B = W^T, W is [N,K] row-major)
    gemm_h<true, MODE_FWD><<<gH, blk, SMEM_BYTES>>>(xm1, wz0, DIN,
        nullptr, nullptr, 0, nullptr, nullptr, 0, nullptr, nullptr, 0,
        HID, bz0, nullptr, nullptr, s1, a1, nullptr);
    gemm_h<true, MODE_FWD><<<gH, blk, SMEM_BYTES>>>(a1, wz1, HID,
        xm1, wx0, DIN, nullptr, nullptr, 0, nullptr, nullptr, 0,
        HID, bx0, nullptr, nullptr, s2, a2, nullptr);
    gemm_h<true, MODE_FWD><<<gH, blk, SMEM_BYTES>>>(a2, wz2, HID,
        xm1, wx1, DIN, nullptr, nullptr, 0, nullptr, nullptr, 0,
        HID, bx1, nullptr, nullptr, s3, a3, nullptr);
    gemm_h<true, MODE_L4><<<gH, blk, SMEM_BYTES>>>(a3, wz3, HID,
        xm1, wx2, DIN, nullptr, nullptr, 0, nullptr, nullptr, 0,
        HID, bx2, WzL, nullptr, d4, nullptr, nullptr);

    // Backward: d_k = s_k * (d_{k+1} @ Wz_{k+1}); Wz [K,N] row-major -> BT=false
    gemm_h<false, MODE_BWD><<<gH, blk, SMEM_BYTES>>>(d4, wz3, HID,
        nullptr, nullptr, 0, nullptr, nullptr, 0, nullptr, nullptr, 0,
        HID, nullptr, nullptr, s3, d3, nullptr, nullptr);
    gemm_h<false, MODE_BWD><<<gH, blk, SMEM_BYTES>>>(d3, wz2, HID,
        nullptr, nullptr, 0, nullptr, nullptr, 0, nullptr, nullptr, 0,
        HID, nullptr, nullptr, s2, d2, nullptr, nullptr);
    gemm_h<false, MODE_BWD><<<gH, blk, SMEM_BYTES>>>(d2, wz1, HID,
        nullptr, nullptr, 0, nullptr, nullptr, 0, nullptr, nullptr, 0,
        HID, nullptr, nullptr, s1, d1, nullptr, nullptr);

    // Final: action = WxL + d1@Wz0 + d2@Wx0 + d3@Wx1 + d4@Wx2 (all [HID,DIN] = [K,N])
    gemm_h<false, MODE_FIN><<<gF, blk, SMEM_BYTES>>>(d1, wz0, HID,
        d2, wx0, HID, d3, wx1, HID, d4, wx2, HID,
        DIN, nullptr, WxL, nullptr, nullptr, nullptr, out);
}

// round 15
// speedup vs baseline: 1.2879x; 1.2879x over previous
#include <cuda_runtime.h>
#include <cuda_fp16.h>
#include <mma.h>
#include <math.h>
#include <cstdint>

using namespace nvcuda;

// Problem shapes
#define BATCH 65536
#define DIN   64
#define HID   512

// GEMM tile config (fp16 operands, fp32 accum) — R10/R12 proven config
#define BM 128
#define BN 128
#define BKC 64
#define LDA_H 72     // 64 + 8 pad halfs
#define LDB_H 144    // 128 + 16 pad halfs
#define NTHREADS 256
#define STAGES 3

#define A_STAGE_HALFS (BM * LDA_H)     // 9216
#define W_STAGE_HALFS 9216             // max(128*72, 64*144)
#define STAGE_HALFS  (A_STAGE_HALFS + W_STAGE_HALFS)   // 18432
#define SMEM_BYTES   (STAGES * STAGE_HALFS * 2)        // 110592 -> 2 CTAs/SM

// final-GEMM (N=64) specialization
#define LDBF_H 72
#define BF_STAGE_HALFS (64 * LDBF_H)                   // 4608
#define STAGEF_HALFS (A_STAGE_HALFS + BF_STAGE_HALFS)  // 13824
#define SMEMF_BYTES  (STAGES * STAGEF_HALFS * 2)       // 82944 -> 2 CTAs/SM

// ---------------- scratch ----------------
__device__ __align__(256) __half g_xm1[BATCH * DIN];
__device__ __align__(256) __half g_s1[BATCH * HID];
__device__ __align__(256) __half g_s2[BATCH * HID];
__device__ __align__(256) __half g_s3[BATCH * HID];
__device__ __align__(256) __half g_a1[BATCH * HID];
__device__ __align__(256) __half g_a2[BATCH * HID];
__device__ __align__(256) __half g_a3[BATCH * HID];
__device__ __align__(256) __half g_d1[BATCH * HID];
__device__ __align__(256) __half g_d2[BATCH * HID];
__device__ __align__(256) __half g_d3[BATCH * HID];
__device__ __align__(256) __half g_d4[BATCH * HID];
__device__ __align__(256) __half g_wz0[HID * DIN];
__device__ __align__(256) __half g_wz1[HID * HID];
__device__ __align__(256) __half g_wz2[HID * HID];
__device__ __align__(256) __half g_wz3[HID * HID];
__device__ __align__(256) __half g_wx0[HID * DIN];
__device__ __align__(256) __half g_wx1[HID * DIN];
__device__ __align__(256) __half g_wx2[HID * DIN];

// ---------------- prep kernels ----------------
__global__ void sub1_half_kernel(const float* __restrict__ in, __half* __restrict__ out, int n) {
    int i = blockIdx.x * blockDim.x + threadIdx.x;
    if (i < n) out[i] = __float2half_rn(in[i] - 1.0f);
}

__global__ void prep_weights(
    const float* __restrict__ Wz0, const float* __restrict__ Wx0,
    const float* __restrict__ Wx1, const float* __restrict__ Wx2,
    const float* __restrict__ Wz1, const float* __restrict__ Wz2, const float* __restrict__ Wz3,
    __half* __restrict__ wz0, __half* __restrict__ wx0,
    __half* __restrict__ wx1, __half* __restrict__ wx2,
    __half* __restrict__ wz1, __half* __restrict__ wz2, __half* __restrict__ wz3)
{
    const int S = HID * DIN;
    const int L = HID * HID;
    int i = blockIdx.x * blockDim.x + threadIdx.x;
    if (i < 4 * S) {
        int seg = i / S, off = i - seg * S;
        const float* src = (seg == 0) ? Wz0 : (seg == 1) ? Wx0 : (seg == 2) ? Wx1 : Wx2;
        __half* dst      = (seg == 0) ? wz0 : (seg == 1) ? wx0 : (seg == 2) ? wx1 : wx2;
        dst[off] = __float2half_rn(src[off]);
    } else {
        int j = i - 4 * S;
        if (j < 3 * L) {
            int seg = j / L, off = j - seg * L;
            const float* src = (seg == 0) ? Wz1 : (seg == 1) ? Wz2 : Wz3;
            __half* dst      = (seg == 0) ? wz1 : (seg == 1) ? wz2 : wz3;
            dst[off] = __float2half_rn(src[off]);
        }
    }
}

// ---------------- helpers ----------------
__device__ __forceinline__ float softplusf(float p) { return (p > 20.0f) ? p : log1pf(expf(p)); }
__device__ __forceinline__ float sigmoidf_(float p) { return 1.0f / (1.0f + expf(-p)); }

__device__ __forceinline__ void cp_async16(__half* smem_dst, const __half* gmem_src, bool pred) {
    unsigned int s = (unsigned int)__cvta_generic_to_shared(smem_dst);
    int bytes = pred ? 16 : 0;
    asm volatile("cp.async.cg.shared.global [%0], [%1], 16, %2;\n"
                 :: "r"(s), "l"(gmem_src), "r"(bytes));
}
__device__ __forceinline__ void cp_commit() { asm volatile("cp.async.commit_group;\n" ::: "memory"); }
__device__ __forceinline__ void cp_wait0() { asm volatile("cp.async.wait_group 0;\n" ::: "memory"); }
__device__ __forceinline__ void cp_wait1() { asm volatile("cp.async.wait_group 1;\n" ::: "memory"); }

// Epilogue modes
#define MODE_FWD 0
#define MODE_L4  1
#define MODE_BWD 2
#define MODE_FIN 3

__device__ __forceinline__ void get_iter(
    int it,
    const __half* A0, const __half* W0, int K0,
    const __half* A1, const __half* W1, int K1,
    const __half* A2, const __half* W2, int K2,
    const __half* A3, const __half* W3, int K3,
    const __half*& A, const __half*& W, int& K, int& k0)
{
    int n0 = K0 >> 6;
    if (it < n0) { A = A0; W = W0; K = K0; k0 = it << 6; return; }
    it -= n0;
    int n1 = K1 >> 6;
    if (it < n1) { A = A1; W = W1; K = K1; k0 = it << 6; return; }
    it -= n1;
    int n2 = K2 >> 6;
    if (it < n2) { A = A2; W = W2; K = K2; k0 = it << 6; return; }
    it -= n2;
    A = A3; W = W3; K = K3; k0 = it << 6;
}

// Stage one K-chunk: A tile [128 x 64] halfs; W tile.
// BT=true : W [N,K] row-major -> sW[n*LDA_H + k]
// BT=false: W [K,N] row-major -> sW[k*LDB_H + n]
template<bool BT>
__device__ __forceinline__ void stage_tiles(
    __half* sA, __half* sW,
    const __half* __restrict__ A, const __half* __restrict__ W,
    int K, int k0, int m0, int n0, int N, int tid)
{
    #pragma unroll
    for (int t = 0; t < 4; t++) {
        int slot = tid + t * NTHREADS;
        int row = slot >> 3, kq = slot & 7;
        cp_async16(&sA[row * LDA_H + (kq << 3)],
                   A + (size_t)(m0 + row) * K + k0 + (kq << 3), true);
    }
    if (BT) {
        #pragma unroll
        for (int t = 0; t < 4; t++) {
            int slot = tid + t * NTHREADS;
            int n = slot >> 3, kq = slot & 7;
            cp_async16(&sW[n * LDA_H + (kq << 3)],
                       W + (size_t)(n0 + n) * K + k0 + (kq << 3), true);
        }
    } else {
        #pragma unroll
        for (int t = 0; t < 4; t++) {
            int slot = tid + t * NTHREADS;
            int krow = slot >> 4, nq = slot & 15;
            int col = n0 + (nq << 3);
            cp_async16(&sW[krow * LDB_H + (nq << 3)],
                       W + (size_t)(k0 + krow) * N + col, col < N);
        }
    }
}

// fp16 fused GEMM, 3-stage cp.async ring, one __syncthreads per iteration.
template<bool BT, int MODE>
__global__ void __launch_bounds__(NTHREADS, 2)
gemm_h(const __half* __restrict__ A0, const __half* __restrict__ W0, int K0,
       const __half* __restrict__ A1, const __half* __restrict__ W1, int K1,
       const __half* __restrict__ A2, const __half* __restrict__ W2, int K2,
       const __half* __restrict__ A3, const __half* __restrict__ W3, int K3,
       int N,
       const float* __restrict__ bias,
       const float* __restrict__ vecn,
       const __half* __restrict__ sgate,
       __half* __restrict__ out1h,
       __half* __restrict__ out2h,
       float* __restrict__ out1f)
{
    extern __shared__ __half smem_h[];

    const int tid    = threadIdx.x;
    const int warpId = tid >> 5;
    const int lane   = tid & 31;
    const int wm     = warpId >> 2;   // 0..1
    const int wn     = warpId & 3;    // 0..3
    const int m0     = blockIdx.y * BM;
    const int n0     = blockIdx.x * BN;

    wmma::fragment<wmma::accumulator, 16, 16, 16, float> acc[4][2];
    #pragma unroll
    for (int i = 0; i < 4; i++)
        #pragma unroll
        for (int j = 0; j < 2; j++)
            wmma::fill_fragment(acc[i][j], 0.0f);

    const int niter = (K0 >> 6) + (K1 >> 6) + (K2 >> 6) + (K3 >> 6);

    // prologue: stage chunk 0 and 1
    #pragma unroll
    for (int j = 0; j < 2; j++) {
        if (j < niter) {
            const __half *A, *W; int K, k0;
            get_iter(j, A0,W0,K0, A1,W1,K1, A2,W2,K2, A3,W3,K3, A, W, K, k0);
            stage_tiles<BT>(smem_h + j * STAGE_HALFS,
                            smem_h + j * STAGE_HALFS + A_STAGE_HALFS,
                            A, W, K, k0, m0, n0, N, tid);
            cp_commit();
        }
    }

    for (int it = 0; it < niter; ++it) {
        if (it + 1 < niter) cp_wait1(); else cp_wait0();
        __syncthreads();

        const int nxt = it + 2;
        if (nxt < niter) {
            const __half *A, *W; int K, k0;
            get_iter(nxt, A0,W0,K0, A1,W1,K1, A2,W2,K2, A3,W3,K3, A, W, K, k0);
            __half* nb = smem_h + (nxt % STAGES) * STAGE_HALFS;
            stage_tiles<BT>(nb, nb + A_STAGE_HALFS, A, W, K, k0, m0, n0, N, tid);
            cp_commit();
        }

        __half* sA = smem_h + (it % STAGES) * STAGE_HALFS;
        __half* sW = sA + A_STAGE_HALFS;

        #pragma unroll
        for (int kk = 0; kk < BKC; kk += 16) {
            wmma::fragment<wmma::matrix_a, 16, 16, 16, __half, wmma::row_major> af[4];
            #pragma unroll
            for (int i = 0; i < 4; i++)
                wmma::load_matrix_sync(af[i], &sA[(wm * 64 + i * 16) * LDA_H + kk], LDA_H);
            if (BT) {
                wmma::fragment<wmma::matrix_b, 16, 16, 16, __half, wmma::col_major> bf[2];
                #pragma unroll
                for (int j = 0; j < 2; j++)
                    wmma::load_matrix_sync(bf[j], &sW[(wn * 32 + j * 16) * LDA_H + kk], LDA_H);
                #pragma unroll
                for (int i = 0; i < 4; i++)
                    #pragma unroll
                    for (int j = 0; j < 2; j++)
                        wmma::mma_sync(acc[i][j], af[i], bf[j], acc[i][j]);
            } else {
                wmma::fragment<wmma::matrix_b, 16, 16, 16, __half, wmma::row_major> bf[2];
                #pragma unroll
                for (int j = 0; j < 2; j++)
                    wmma::load_matrix_sync(bf[j], &sW[kk * LDB_H + wn * 32 + j * 16], LDB_H);
                #pragma unroll
                for (int i = 0; i < 4; i++)
                    #pragma unroll
                    for (int j = 0; j < 2; j++)
                        wmma::mma_sync(acc[i][j], af[i], bf[j], acc[i][j]);
            }
        }
    }

    // ---- epilogue ----
    __syncthreads();
    float* ep = reinterpret_cast<float*>(smem_h) + warpId * 288;

    #pragma unroll
    for (int i = 0; i < 4; i++) {
        #pragma unroll
        for (int j = 0; j < 2; j++) {
            const int rbase = m0 + wm * 64 + i * 16;
            const int cbase = n0 + wn * 32 + j * 16;
            wmma::store_matrix_sync(ep, acc[i][j], 16, wmma::mem_row_major);
            __syncwarp();
            #pragma unroll
            for (int e = 0; e < 8; e++) {
                int lin = e * 32 + lane;
                int r = lin >> 4;
                int c = lin & 15;
                int col = cbase + c;
                if (col < N) {
                    float p = ep[lin];
                    size_t oi = (size_t)(rbase + r) * N + col;
                    if (MODE == MODE_FWD) {
                        p += bias[col];
                        out1h[oi] = __float2half_rn(sigmoidf_(p));
                        out2h[oi] = __float2half_rn(softplusf(p));
                    } else if (MODE == MODE_L4) {
                        p += bias[col];
                        out1h[oi] = __float2half_rn(vecn[col] * sigmoidf_(p));
                    } else if (MODE == MODE_BWD) {
                        out1h[oi] = __float2half_rn(__half2float(sgate[oi]) * p);
                    } else { // MODE_FIN
                        out1f[oi] = p + vecn[col];
                    }
                }
            }
            __syncwarp();
        }
    }
}

// ---------------- final GEMM: N=64 specialized (BN=64, warp tile 64x16) ----------------
__device__ __forceinline__ void stage_fin(
    __half* sA, __half* sW,
    const __half* __restrict__ A, const __half* __restrict__ W,
    int K, int k0, int m0, int tid)
{
    #pragma unroll
    for (int t = 0; t < 4; t++) {
        int slot = tid + t * NTHREADS;
        int row = slot >> 3, kq = slot & 7;
        cp_async16(&sA[row * LDA_H + (kq << 3)],
                   A + (size_t)(m0 + row) * K + k0 + (kq << 3), true);
    }
    // W [K,64]: 64 k-rows x 8 chunks = 512 chunks, 2/thread
    #pragma unroll
    for (int t = 0; t < 2; t++) {
        int slot = tid + t * NTHREADS;
        int krow = slot >> 3, nq = slot & 7;
        cp_async16(&sW[krow * LDBF_H + (nq << 3)],
                   W + (size_t)(k0 + krow) * DIN + (nq << 3), true);
    }
}

__global__ void __launch_bounds__(NTHREADS, 2)
gemm_fin(const __half* __restrict__ A0, const __half* __restrict__ W0, int K0,
         const __half* __restrict__ A1, const __half* __restrict__ W1, int K1,
         const __half* __restrict__ A2, const __half* __restrict__ W2, int K2,
         const __half* __restrict__ A3, const __half* __restrict__ W3, int K3,
         const float* __restrict__ vecn,
         float* __restrict__ out1f)
{
    extern __shared__ __half smem_h[];

    const int tid    = threadIdx.x;
    const int warpId = tid >> 5;
    const int lane   = tid & 31;
    const int wm     = warpId >> 2;   // 0..1 (64-row slab)
    const int wn     = warpId & 3;    // 0..3 (16-col slab)
    const int m0     = blockIdx.y * BM;

    wmma::fragment<wmma::accumulator, 16, 16, 16, float> acc[4];
    #pragma unroll
    for (int i = 0; i < 4; i++)
        wmma::fill_fragment(acc[i], 0.0f);

    const int niter = (K0 >> 6) + (K1 >> 6) + (K2 >> 6) + (K3 >> 6);

    #pragma unroll
    for (int j = 0; j < 2; j++) {
        if (j < niter) {
            const __half *A, *W; int K, k0;
            get_iter(j, A0,W0,K0, A1,W1,K1, A2,W2,K2, A3,W3,K3, A, W, K, k0);
            stage_fin(smem_h + j * STAGEF_HALFS,
                      smem_h + j * STAGEF_HALFS + A_STAGE_HALFS,
                      A, W, K, k0, m0, tid);
            cp_commit();
        }
    }

    for (int it = 0; it < niter; ++it) {
        if (it + 1 < niter) cp_wait1(); else cp_wait0();
        __syncthreads();

        const int nxt = it + 2;
        if (nxt < niter) {
            const __half *A, *W; int K, k0;
            get_iter(nxt, A0,W0,K0, A1,W1,K1, A2,W2,K2, A3,W3,K3, A, W, K, k0);
            __half* nb = smem_h + (nxt % STAGES) * STAGEF_HALFS;
            stage_fin(nb, nb + A_STAGE_HALFS, A, W, K, k0, m0, tid);
            cp_commit();
        }

        __half* sA = smem_h + (it % STAGES) * STAGEF_HALFS;
        __half* sW = sA + A_STAGE_HALFS;

        #pragma unroll
        for (int kk = 0; kk < BKC; kk += 16) {
            wmma::fragment<wmma::matrix_a, 16, 16, 16, __half, wmma::row_major> af[4];
            #pragma unroll
            for (int i = 0; i < 4; i++)
                wmma::load_matrix_sync(af[i], &sA[(wm * 64 + i * 16) * LDA_H + kk], LDA_H);
            wmma::fragment<wmma::matrix_b, 16, 16, 16, __half, wmma::row_major> bf;
            wmma::load_matrix_sync(bf, &sW[kk * LDBF_H + wn * 16], LDBF_H);
            #pragma unroll
            for (int i = 0; i < 4; i++)
                wmma::mma_sync(acc[i], af[i], bf, acc[i]);
        }
    }

    __syncthreads();
    float* ep = reinterpret_cast<float*>(smem_h) + warpId * 288;

    #pragma unroll
    for (int i = 0; i < 4; i++) {
        const int rbase = m0 + wm * 64 + i * 16;
        const int cbase = wn * 16;
        wmma::store_matrix_sync(ep, acc[i], 16, wmma::mem_row_major);
        __syncwarp();
        #pragma unroll
        for (int e = 0; e < 8; e++) {
            int lin = e * 32 + lane;
            int r = lin >> 4;
            int c = lin & 15;
            int col = cbase + c;
            float p = ep[lin];
            out1f[(size_t)(rbase + r) * DIN + col] = p + vecn[col];
        }
        __syncwarp();
    }
}

// ---------------- host launcher ----------------
extern "C" void kernel_launch(void* const* d_in, const int* in_sizes, int n_in,
                              void* d_out, int out_size)
{
    const float* state = (const float*)d_in[0];
    const float* Wz0   = (const float*)d_in[1];
    const float* bz0   = (const float*)d_in[2];
    const float* Wz1   = (const float*)d_in[3];
    const float* Wz2   = (const float*)d_in[4];
    const float* Wz3   = (const float*)d_in[5];
    const float* WzL   = (const float*)d_in[6];
    const float* Wx0   = (const float*)d_in[7];
    const float* bx0   = (const float*)d_in[8];
    const float* Wx1   = (const float*)d_in[9];
    const float* bx1   = (const float*)d_in[10];
    const float* Wx2   = (const float*)d_in[11];
    const float* bx2   = (const float*)d_in[12];
    const float* WxL   = (const float*)d_in[13];
    float* out = (float*)d_out;

    cudaFuncSetAttribute(gemm_h<true,  MODE_FWD>, cudaFuncAttributeMaxDynamicSharedMemorySize, SMEM_BYTES);
    cudaFuncSetAttribute(gemm_h<true,  MODE_L4>,  cudaFuncAttributeMaxDynamicSharedMemorySize, SMEM_BYTES);
    cudaFuncSetAttribute(gemm_h<false, MODE_BWD>, cudaFuncAttributeMaxDynamicSharedMemorySize, SMEM_BYTES);
    cudaFuncSetAttribute(gemm_fin, cudaFuncAttributeMaxDynamicSharedMemorySize, SMEMF_BYTES);

    void* p;
    __half *xm1, *s1, *s2, *s3, *a1, *a2, *a3, *d1, *d2, *d3, *d4;
    __half *wz0, *wz1, *wz2, *wz3, *wx0, *wx1, *wx2;
    cudaGetSymbolAddress(&p, g_xm1);  xm1  = (__half*)p;
    cudaGetSymbolAddress(&p, g_s1);   s1   = (__half*)p;
    cudaGetSymbolAddress(&p, g_s2);   s2   = (__half*)p;
    cudaGetSymbolAddress(&p, g_s3);   s3   = (__half*)p;
    cudaGetSymbolAddress(&p, g_a1);   a1   = (__half*)p;
    cudaGetSymbolAddress(&p, g_a2);   a2   = (__half*)p;
    cudaGetSymbolAddress(&p, g_a3);   a3   = (__half*)p;
    cudaGetSymbolAddress(&p, g_d1);   d1   = (__half*)p;
    cudaGetSymbolAddress(&p, g_d2);   d2   = (__half*)p;
    cudaGetSymbolAddress(&p, g_d3);   d3   = (__half*)p;
    cudaGetSymbolAddress(&p, g_d4);   d4   = (__half*)p;
    cudaGetSymbolAddress(&p, g_wz0);  wz0  = (__half*)p;
    cudaGetSymbolAddress(&p, g_wz1);  wz1  = (__half*)p;
    cudaGetSymbolAddress(&p, g_wz2);  wz2  = (__half*)p;
    cudaGetSymbolAddress(&p, g_wz3);  wz3  = (__half*)p;
    cudaGetSymbolAddress(&p, g_wx0);  wx0  = (__half*)p;
    cudaGetSymbolAddress(&p, g_wx1);  wx1  = (__half*)p;
    cudaGetSymbolAddress(&p, g_wx2);  wx2  = (__half*)p;

    const int nX = BATCH * DIN;
    sub1_half_kernel<<<(nX + 255) / 256, 256>>>(state, xm1, nX);

    const int nW = 4 * HID * DIN + 3 * HID * HID;
    prep_weights<<<(nW + 255) / 256, 256>>>(Wz0, Wx0, Wx1, Wx2, Wz1, Wz2, Wz3,
                                            wz0, wx0, wx1, wx2, wz1, wz2, wz3);

    dim3 blk(NTHREADS);
    dim3 gH(HID / BN, BATCH / BM);   // (4, 512)
    dim3 gF(1, BATCH / BM);          // (1, 512)

    // Forward (BT=true: B = W^T, W is [N,K] row-major)
    gemm_h<true, MODE_FWD><<<gH, blk, SMEM_BYTES>>>(xm1, wz0, DIN,
        nullptr, nullptr, 0, nullptr, nullptr, 0, nullptr, nullptr, 0,
        HID, bz0, nullptr, nullptr, s1, a1, nullptr);
    gemm_h<true, MODE_FWD><<<gH, blk, SMEM_BYTES>>>(a1, wz1, HID,
        xm1, wx0, DIN, nullptr, nullptr, 0, nullptr, nullptr, 0,
        HID, bx0, nullptr, nullptr, s2, a2, nullptr);
    gemm_h<true, MODE_FWD><<<gH, blk, SMEM_BYTES>>>(a2, wz2, HID,
        xm1, wx1, DIN, nullptr, nullptr, 0, nullptr, nullptr, 0,
        HID, bx1, nullptr, nullptr, s3, a3, nullptr);
    gemm_h<true, MODE_L4><<<gH, blk, SMEM_BYTES>>>(a3, wz3, HID,
        xm1, wx2, DIN, nullptr, nullptr, 0, nullptr, nullptr, 0,
        HID, bx2, WzL, nullptr, d4, nullptr, nullptr);

    // Backward: d_k = s_k * (d_{k+1} @ Wz_{k+1}); Wz [K,N] row-major -> BT=false
    gemm_h<false, MODE_BWD><<<gH, blk, SMEM_BYTES>>>(d4, wz3, HID,
        nullptr, nullptr, 0, nullptr, nullptr, 0, nullptr, nullptr, 0,
        HID, nullptr, nullptr, s3, d3, nullptr, nullptr);
    gemm_h<false, MODE_BWD><<<gH, blk, SMEM_BYTES>>>(d3, wz2, HID,
        nullptr, nullptr, 0, nullptr, nullptr, 0, nullptr, nullptr, 0,
        HID, nullptr, nullptr, s2, d2, nullptr, nullptr);
    gemm_h<false, MODE_BWD><<<gH, blk, SMEM_BYTES>>>(d2, wz1, HID,
        nullptr, nullptr, 0, nullptr, nullptr, 0, nullptr, nullptr, 0,
        HID, nullptr, nullptr, s1, d1, nullptr, nullptr);

    // Final: action = WxL + d1@Wz0 + d2@Wx0 + d3@Wx1 + d4@Wx2 (all [HID,DIN] = [K,N], N=64)
    gemm_fin<<<gF, blk, SMEMF_BYTES>>>(d1, wz0, HID,
        d2, wx0, HID, d3, wx1, HID, d4, wx2, HID,
        WxL, out);
}

// round 16
// speedup vs baseline: 1.4936x; 1.1597x over previous
#include <cuda_runtime.h>
#include <cuda_fp16.h>
#include <mma.h>
#include <math.h>
#include <cstdint>

using namespace nvcuda;

// Problem shapes
#define BATCH 65536
#define DIN   64
#define HID   512

// GEMM tile config (fp16 operands, fp32 accum) — R10/R12 proven config
#define BM 128
#define BN 128
#define BKC 64
#define LDA_H 72     // 64 + 8 pad halfs
#define LDB_H 144    // 128 + 16 pad halfs
#define NTHREADS 256
#define STAGES 3

#define A_STAGE_HALFS (BM * LDA_H)     // 9216
#define W_STAGE_HALFS 9216             // max(128*72, 64*144)
#define STAGE_HALFS  (A_STAGE_HALFS + W_STAGE_HALFS)   // 18432
#define SMEM_BYTES   (STAGES * STAGE_HALFS * 2)        // 110592 -> 2 CTAs/SM

// final-GEMM (N=64) specialization
#define LDBF_H 72
#define BF_STAGE_HALFS (64 * LDBF_H)                   // 4608
#define STAGEF_HALFS (A_STAGE_HALFS + BF_STAGE_HALFS)  // 13824
#define SMEMF_BYTES  (STAGES * STAGEF_HALFS * 2)       // 82944 -> 2 CTAs/SM

// ---------------- scratch ----------------
__device__ __align__(256) __half g_xm1[BATCH * DIN];
__device__ __align__(256) __half g_s1[BATCH * HID];
__device__ __align__(256) __half g_s2[BATCH * HID];
__device__ __align__(256) __half g_s3[BATCH * HID];
__device__ __align__(256) __half g_a1[BATCH * HID];
__device__ __align__(256) __half g_a2[BATCH * HID];
__device__ __align__(256) __half g_a3[BATCH * HID];
__device__ __align__(256) __half g_d1[BATCH * HID];
__device__ __align__(256) __half g_d2[BATCH * HID];
__device__ __align__(256) __half g_d3[BATCH * HID];
__device__ __align__(256) __half g_d4[BATCH * HID];
__device__ __align__(256) __half g_wz0[HID * DIN];
__device__ __align__(256) __half g_wz1[HID * HID];
__device__ __align__(256) __half g_wz2[HID * HID];
__device__ __align__(256) __half g_wz3[HID * HID];
__device__ __align__(256) __half g_wx0[HID * DIN];
__device__ __align__(256) __half g_wx1[HID * DIN];
__device__ __align__(256) __half g_wx2[HID * DIN];

// ---------------- prep kernel: x-1 conversion + ALL weight conversions ----------------
__global__ void prep_all(
    const float* __restrict__ state,
    const float* __restrict__ Wz0, const float* __restrict__ Wx0,
    const float* __restrict__ Wx1, const float* __restrict__ Wx2,
    const float* __restrict__ Wz1, const float* __restrict__ Wz2, const float* __restrict__ Wz3,
    __half* __restrict__ xm1,
    __half* __restrict__ wz0, __half* __restrict__ wx0,
    __half* __restrict__ wx1, __half* __restrict__ wx2,
    __half* __restrict__ wz1, __half* __restrict__ wz2, __half* __restrict__ wz3)
{
    const int NX = BATCH * DIN;       // 4194304
    const int S  = HID * DIN;         // 32768
    const int L  = HID * HID;         // 262144
    int i = blockIdx.x * blockDim.x + threadIdx.x;
    if (i < NX) {
        xm1[i] = __float2half_rn(state[i] - 1.0f);
        return;
    }
    int j = i - NX;
    if (j < 4 * S) {
        int seg = j / S, off = j - seg * S;
        const float* src = (seg == 0) ? Wz0 : (seg == 1) ? Wx0 : (seg == 2) ? Wx1 : Wx2;
        __half* dst      = (seg == 0) ? wz0 : (seg == 1) ? wx0 : (seg == 2) ? wx1 : wx2;
        dst[off] = __float2half_rn(src[off]);
        return;
    }
    j -= 4 * S;
    if (j < 3 * L) {
        int seg = j / L, off = j - seg * L;
        const float* src = (seg == 0) ? Wz1 : (seg == 1) ? Wz2 : Wz3;
        __half* dst      = (seg == 0) ? wz1 : (seg == 1) ? wz2 : wz3;
        dst[off] = __float2half_rn(src[off]);
    }
}

// ---------------- helpers ----------------
__device__ __forceinline__ float softplusf(float p) { return (p > 20.0f) ? p : log1pf(expf(p)); }
__device__ __forceinline__ float sigmoidf_(float p) { return 1.0f / (1.0f + expf(-p)); }

__device__ __forceinline__ void cp_async16(__half* smem_dst, const __half* gmem_src) {
    unsigned int s = (unsigned int)__cvta_generic_to_shared(smem_dst);
    asm volatile("cp.async.cg.shared.global [%0], [%1], 16;\n"
                 :: "r"(s), "l"(gmem_src));
}
__device__ __forceinline__ void cp_commit() { asm volatile("cp.async.commit_group;\n" ::: "memory"); }
__device__ __forceinline__ void cp_wait0() { asm volatile("cp.async.wait_group 0;\n" ::: "memory"); }
__device__ __forceinline__ void cp_wait1() { asm volatile("cp.async.wait_group 1;\n" ::: "memory"); }

// Epilogue modes
#define MODE_FWD 0
#define MODE_L4  1
#define MODE_BWD 2

__device__ __forceinline__ void get_iter(
    int it,
    const __half* A0, const __half* W0, int K0,
    const __half* A1, const __half* W1, int K1,
    const __half* A2, const __half* W2, int K2,
    const __half* A3, const __half* W3, int K3,
    const __half*& A, const __half*& W, int& K, int& k0)
{
    int n0 = K0 >> 6;
    if (it < n0) { A = A0; W = W0; K = K0; k0 = it << 6; return; }
    it -= n0;
    int n1 = K1 >> 6;
    if (it < n1) { A = A1; W = W1; K = K1; k0 = it << 6; return; }
    it -= n1;
    int n2 = K2 >> 6;
    if (it < n2) { A = A2; W = W2; K = K2; k0 = it << 6; return; }
    it -= n2;
    A = A3; W = W3; K = K3; k0 = it << 6;
}

// Stage one K-chunk: A tile [128 x 64] halfs; W tile.
// BT=true : W [N,K] row-major -> sW[n*LDA_H + k]
// BT=false: W [K,N] row-major (N==HID for all uses) -> sW[k*LDB_H + n]
template<bool BT>
__device__ __forceinline__ void stage_tiles(
    __half* sA, __half* sW,
    const __half* __restrict__ A, const __half* __restrict__ W,
    int K, int k0, int m0, int n0, int N, int tid)
{
    #pragma unroll
    for (int t = 0; t < 4; t++) {
        int slot = tid + t * NTHREADS;
        int row = slot >> 3, kq = slot & 7;
        cp_async16(&sA[row * LDA_H + (kq << 3)],
                   A + (size_t)(m0 + row) * K + k0 + (kq << 3));
    }
    if (BT) {
        #pragma unroll
        for (int t = 0; t < 4; t++) {
            int slot = tid + t * NTHREADS;
            int n = slot >> 3, kq = slot & 7;
            cp_async16(&sW[n * LDA_H + (kq << 3)],
                       W + (size_t)(n0 + n) * K + k0 + (kq << 3));
        }
    } else {
        #pragma unroll
        for (int t = 0; t < 4; t++) {
            int slot = tid + t * NTHREADS;
            int krow = slot >> 4, nq = slot & 15;
            int col = n0 + (nq << 3);
            cp_async16(&sW[krow * LDB_H + (nq << 3)],
                       W + (size_t)(k0 + krow) * N + col);
        }
    }
}

// fp16 fused GEMM, 3-stage cp.async ring, one __syncthreads per iteration.
template<bool BT, int MODE>
__global__ void __launch_bounds__(NTHREADS, 2)
gemm_h(const __half* __restrict__ A0, const __half* __restrict__ W0, int K0,
       const __half* __restrict__ A1, const __half* __restrict__ W1, int K1,
       const __half* __restrict__ A2, const __half* __restrict__ W2, int K2,
       const __half* __restrict__ A3, const __half* __restrict__ W3, int K3,
       int N,
       const float* __restrict__ bias,
       const float* __restrict__ vecn,
       const __half* __restrict__ sgate,
       __half* __restrict__ out1h,
       __half* __restrict__ out2h)
{
    extern __shared__ __half smem_h[];

    const int tid    = threadIdx.x;
    const int warpId = tid >> 5;
    const int lane   = tid & 31;
    const int wm     = warpId >> 2;   // 0..1
    const int wn     = warpId & 3;    // 0..3
    const int m0     = blockIdx.y * BM;
    const int n0     = blockIdx.x * BN;

    wmma::fragment<wmma::accumulator, 16, 16, 16, float> acc[4][2];
    #pragma unroll
    for (int i = 0; i < 4; i++)
        #pragma unroll
        for (int j = 0; j < 2; j++)
            wmma::fill_fragment(acc[i][j], 0.0f);

    const int niter = (K0 >> 6) + (K1 >> 6) + (K2 >> 6) + (K3 >> 6);

    // prologue: stage chunk 0 and 1
    #pragma unroll
    for (int j = 0; j < 2; j++) {
        if (j < niter) {
            const __half *A, *W; int K, k0;
            get_iter(j, A0,W0,K0, A1,W1,K1, A2,W2,K2, A3,W3,K3, A, W, K, k0);
            stage_tiles<BT>(smem_h + j * STAGE_HALFS,
                            smem_h + j * STAGE_HALFS + A_STAGE_HALFS,
                            A, W, K, k0, m0, n0, N, tid);
            cp_commit();
        }
    }

    for (int it = 0; it < niter; ++it) {
        if (it + 1 < niter) cp_wait1(); else cp_wait0();
        __syncthreads();

        const int nxt = it + 2;
        if (nxt < niter) {
            const __half *A, *W; int K, k0;
            get_iter(nxt, A0,W0,K0, A1,W1,K1, A2,W2,K2, A3,W3,K3, A, W, K, k0);
            __half* nb = smem_h + (nxt % STAGES) * STAGE_HALFS;
            stage_tiles<BT>(nb, nb + A_STAGE_HALFS, A, W, K, k0, m0, n0, N, tid);
            cp_commit();
        }

        __half* sA = smem_h + (it % STAGES) * STAGE_HALFS;
        __half* sW = sA + A_STAGE_HALFS;

        #pragma unroll
        for (int kk = 0; kk < BKC; kk += 16) {
            wmma::fragment<wmma::matrix_a, 16, 16, 16, __half, wmma::row_major> af[4];
            #pragma unroll
            for (int i = 0; i < 4; i++)
                wmma::load_matrix_sync(af[i], &sA[(wm * 64 + i * 16) * LDA_H + kk], LDA_H);
            if (BT) {
                wmma::fragment<wmma::matrix_b, 16, 16, 16, __half, wmma::col_major> bf[2];
                #pragma unroll
                for (int j = 0; j < 2; j++)
                    wmma::load_matrix_sync(bf[j], &sW[(wn * 32 + j * 16) * LDA_H + kk], LDA_H);
                #pragma unroll
                for (int i = 0; i < 4; i++)
                    #pragma unroll
                    for (int j = 0; j < 2; j++)
                        wmma::mma_sync(acc[i][j], af[i], bf[j], acc[i][j]);
            } else {
                wmma::fragment<wmma::matrix_b, 16, 16, 16, __half, wmma::row_major> bf[2];
                #pragma unroll
                for (int j = 0; j < 2; j++)
                    wmma::load_matrix_sync(bf[j], &sW[kk * LDB_H + wn * 32 + j * 16], LDB_H);
                #pragma unroll
                for (int i = 0; i < 4; i++)
                    #pragma unroll
                    for (int j = 0; j < 2; j++)
                        wmma::mma_sync(acc[i][j], af[i], bf[j], acc[i][j]);
            }
        }
    }

    // ---- epilogue ----
    __syncthreads();
    float* ep = reinterpret_cast<float*>(smem_h) + warpId * 288;

    #pragma unroll
    for (int i = 0; i < 4; i++) {
        #pragma unroll
        for (int j = 0; j < 2; j++) {
            const int rbase = m0 + wm * 64 + i * 16;
            const int cbase = n0 + wn * 32 + j * 16;
            wmma::store_matrix_sync(ep, acc[i][j], 16, wmma::mem_row_major);
            __syncwarp();
            #pragma unroll
            for (int e = 0; e < 8; e++) {
                int lin = e * 32 + lane;
                int r = lin >> 4;
                int c = lin & 15;
                int col = cbase + c;
                float p = ep[lin];
                size_t oi = (size_t)(rbase + r) * N + col;
                if (MODE == MODE_FWD) {
                    p += bias[col];
                    out1h[oi] = __float2half_rn(sigmoidf_(p));
                    out2h[oi] = __float2half_rn(softplusf(p));
                } else if (MODE == MODE_L4) {
                    p += bias[col];
                    out1h[oi] = __float2half_rn(vecn[col] * sigmoidf_(p));
                } else { // MODE_BWD
                    out1h[oi] = __float2half_rn(__half2float(sgate[oi]) * p);
                }
            }
            __syncwarp();
        }
    }
}

// ---------------- final GEMM: N=64 specialized (BN=64, warp tile 64x16) ----------------
__device__ __forceinline__ void stage_fin(
    __half* sA, __half* sW,
    const __half* __restrict__ A, const __half* __restrict__ W,
    int K, int k0, int m0, int tid)
{
    #pragma unroll
    for (int t = 0; t < 4; t++) {
        int slot = tid + t * NTHREADS;
        int row = slot >> 3, kq = slot & 7;
        cp_async16(&sA[row * LDA_H + (kq << 3)],
                   A + (size_t)(m0 + row) * K + k0 + (kq << 3));
    }
    // W [K,64]: 64 k-rows x 8 chunks = 512 chunks, 2/thread
    #pragma unroll
    for (int t = 0; t < 2; t++) {
        int slot = tid + t * NTHREADS;
        int krow = slot >> 3, nq = slot & 7;
        cp_async16(&sW[krow * LDBF_H + (nq << 3)],
                   W + (size_t)(k0 + krow) * DIN + (nq << 3));
    }
}

__global__ void __launch_bounds__(NTHREADS, 2)
gemm_fin(const __half* __restrict__ A0, const __half* __restrict__ W0, int K0,
         const __half* __restrict__ A1, const __half* __restrict__ W1, int K1,
         const __half* __restrict__ A2, const __half* __restrict__ W2, int K2,
         const __half* __restrict__ A3, const __half* __restrict__ W3, int K3,
         const float* __restrict__ vecn,
         float* __restrict__ out1f)
{
    extern __shared__ __half smem_h[];

    const int tid    = threadIdx.x;
    const int warpId = tid >> 5;
    const int lane   = tid & 31;
    const int wm     = warpId >> 2;   // 0..1 (64-row slab)
    const int wn     = warpId & 3;    // 0..3 (16-col slab)
    const int m0     = blockIdx.y * BM;

    wmma::fragment<wmma::accumulator, 16, 16, 16, float> acc[4];
    #pragma unroll
    for (int i = 0; i < 4; i++)
        wmma::fill_fragment(acc[i], 0.0f);

    const int niter = (K0 >> 6) + (K1 >> 6) + (K2 >> 6) + (K3 >> 6);

    #pragma unroll
    for (int j = 0; j < 2; j++) {
        if (j < niter) {
            const __half *A, *W; int K, k0;
            get_iter(j, A0,W0,K0, A1,W1,K1, A2,W2,K2, A3,W3,K3, A, W, K, k0);
            stage_fin(smem_h + j * STAGEF_HALFS,
                      smem_h + j * STAGEF_HALFS + A_STAGE_HALFS,
                      A, W, K, k0, m0, tid);
            cp_commit();
        }
    }

    for (int it = 0; it < niter; ++it) {
        if (it + 1 < niter) cp_wait1(); else cp_wait0();
        __syncthreads();

        const int nxt = it + 2;
        if (nxt < niter) {
            const __half *A, *W; int K, k0;
            get_iter(nxt, A0,W0,K0, A1,W1,K1, A2,W2,K2, A3,W3,K3, A, W, K, k0);
            __half* nb = smem_h + (nxt % STAGES) * STAGEF_HALFS;
            stage_fin(nb, nb + A_STAGE_HALFS, A, W, K, k0, m0, tid);
            cp_commit();
        }

        __half* sA = smem_h + (it % STAGES) * STAGEF_HALFS;
        __half* sW = sA + A_STAGE_HALFS;

        #pragma unroll
        for (int kk = 0; kk < BKC; kk += 16) {
            wmma::fragment<wmma::matrix_a, 16, 16, 16, __half, wmma::row_major> af[4];
            #pragma unroll
            for (int i = 0; i < 4; i++)
                wmma::load_matrix_sync(af[i], &sA[(wm * 64 + i * 16) * LDA_H + kk], LDA_H);
            wmma::fragment<wmma::matrix_b, 16, 16, 16, __half, wmma::row_major> bf;
            wmma::load_matrix_sync(bf, &sW[kk * LDBF_H + wn * 16], LDBF_H);
            #pragma unroll
            for (int i = 0; i < 4; i++)
                wmma::mma_sync(acc[i], af[i], bf, acc[i]);
        }
    }

    __syncthreads();
    float* ep = reinterpret_cast<float*>(smem_h) + warpId * 288;

    #pragma unroll
    for (int i = 0; i < 4; i++) {
        const int rbase = m0 + wm * 64 + i * 16;
        const int cbase = wn * 16;
        wmma::store_matrix_sync(ep, acc[i], 16, wmma::mem_row_major);
        __syncwarp();
        #pragma unroll
        for (int e = 0; e < 8; e++) {
            int lin = e * 32 + lane;
            int r = lin >> 4;
            int c = lin & 15;
            int col = cbase + c;
            float p = ep[lin];
            out1f[(size_t)(rbase + r) * DIN + col] = p + vecn[col];
        }
        __syncwarp();
    }
}

// ---------------- host launcher ----------------
extern "C" void kernel_launch(void* const* d_in, const int* in_sizes, int n_in,
                              void* d_out, int out_size)
{
    const float* state = (const float*)d_in[0];
    const float* Wz0   = (const float*)d_in[1];
    const float* bz0   = (const float*)d_in[2];
    const float* Wz1   = (const float*)d_in[3];
    const float* Wz2   = (const float*)d_in[4];
    const float* Wz3   = (const float*)d_in[5];
    const float* WzL   = (const float*)d_in[6];
    const float* Wx0   = (const float*)d_in[7];
    const float* bx0   = (const float*)d_in[8];
    const float* Wx1   = (const float*)d_in[9];
    const float* bx1   = (const float*)d_in[10];
    const float* Wx2   = (const float*)d_in[11];
    const float* bx2   = (const float*)d_in[12];
    const float* WxL   = (const float*)d_in[13];
    float* out = (float*)d_out;

    cudaFuncSetAttribute(gemm_h<true,  MODE_FWD>, cudaFuncAttributeMaxDynamicSharedMemorySize, SMEM_BYTES);
    cudaFuncSetAttribute(gemm_h<true,  MODE_L4>,  cudaFuncAttributeMaxDynamicSharedMemorySize, SMEM_BYTES);
    cudaFuncSetAttribute(gemm_h<false, MODE_BWD>, cudaFuncAttributeMaxDynamicSharedMemorySize, SMEM_BYTES);
    cudaFuncSetAttribute(gemm_fin, cudaFuncAttributeMaxDynamicSharedMemorySize, SMEMF_BYTES);

    void* p;
    __half *xm1, *s1, *s2, *s3, *a1, *a2, *a3, *d1, *d2, *d3, *d4;
    __half *wz0, *wz1, *wz2, *wz3, *wx0, *wx1, *wx2;
    cudaGetSymbolAddress(&p, g_xm1);  xm1  = (__half*)p;
    cudaGetSymbolAddress(&p, g_s1);   s1   = (__half*)p;
    cudaGetSymbolAddress(&p, g_s2);   s2   = (__half*)p;
    cudaGetSymbolAddress(&p, g_s3);   s3   = (__half*)p;
    cudaGetSymbolAddress(&p, g_a1);   a1   = (__half*)p;
    cudaGetSymbolAddress(&p, g_a2);   a2   = (__half*)p;
    cudaGetSymbolAddress(&p, g_a3);   a3   = (__half*)p;
    cudaGetSymbolAddress(&p, g_d1);   d1   = (__half*)p;
    cudaGetSymbolAddress(&p, g_d2);   d2   = (__half*)p;
    cudaGetSymbolAddress(&p, g_d3);   d3   = (__half*)p;
    cudaGetSymbolAddress(&p, g_d4);   d4   = (__half*)p;
    cudaGetSymbolAddress(&p, g_wz0);  wz0  = (__half*)p;
    cudaGetSymbolAddress(&p, g_wz1);  wz1  = (__half*)p;
    cudaGetSymbolAddress(&p, g_wz2);  wz2  = (__half*)p;
    cudaGetSymbolAddress(&p, g_wz3);  wz3  = (__half*)p;
    cudaGetSymbolAddress(&p, g_wx0);  wx0  = (__half*)p;
    cudaGetSymbolAddress(&p, g_wx1);  wx1  = (__half*)p;
    cudaGetSymbolAddress(&p, g_wx2);  wx2  = (__half*)p;

    const int nTot = BATCH * DIN + 4 * HID * DIN + 3 * HID * HID;  // 5111808
    prep_all<<<(nTot + 255) / 256, 256>>>(state, Wz0, Wx0, Wx1, Wx2, Wz1, Wz2, Wz3,
                                          xm1, wz0, wx0, wx1, wx2, wz1, wz2, wz3);

    dim3 blk(NTHREADS);
    dim3 gH(HID / BN, BATCH / BM);   // (4, 512)
    dim3 gF(1, BATCH / BM);          // (1, 512)

    // Forward (BT=true: B = W^T, W is [N,K] row-major)
    gemm_h<true, MODE_FWD><<<gH, blk, SMEM_BYTES>>>(xm1, wz0, DIN,
        nullptr, nullptr, 0, nullptr, nullptr, 0, nullptr, nullptr, 0,
        HID, bz0, nullptr, nullptr, s1, a1);
    gemm_h<true, MODE_FWD><<<gH, blk, SMEM_BYTES>>>(a1, wz1, HID,
        xm1, wx0, DIN, nullptr, nullptr, 0, nullptr, nullptr, 0,
        HID, bx0, nullptr, nullptr, s2, a2);
    gemm_h<true, MODE_FWD><<<gH, blk, SMEM_BYTES>>>(a2, wz2, HID,
        xm1, wx1, DIN, nullptr, nullptr, 0, nullptr, nullptr, 0,
        HID, bx1, nullptr, nullptr, s3, a3);
    gemm_h<true, MODE_L4><<<gH, blk, SMEM_BYTES>>>(a3, wz3, HID,
        xm1, wx2, DIN, nullptr, nullptr, 0, nullptr, nullptr, 0,
        HID, bx2, WzL, nullptr, d4, nullptr);

    // Backward: d_k = s_k * (d_{k+1} @ Wz_{k+1}); Wz [K,N] row-major -> BT=false, N=HID
    gemm_h<false, MODE_BWD><<<gH, blk, SMEM_BYTES>>>(d4, wz3, HID,
        nullptr, nullptr, 0, nullptr, nullptr, 0, nullptr, nullptr, 0,
        HID, nullptr, nullptr, s3, d3, nullptr);
    gemm_h<false, MODE_BWD><<<gH, blk, SMEM_BYTES>>>(d3, wz2, HID,
        nullptr, nullptr, 0, nullptr, nullptr, 0, nullptr, nullptr, 0,
        HID, nullptr, nullptr, s2, d2, nullptr);
    gemm_h<false, MODE_BWD><<<gH, blk, SMEM_BYTES>>>(d2, wz1, HID,
        nullptr, nullptr, 0, nullptr, nullptr, 0, nullptr, nullptr, 0,
        HID, nullptr, nullptr, s1, d1, nullptr);

    // Final: action = WxL + d1@Wz0 + d2@Wx0 + d3@Wx1 + d4@Wx2 (all [HID,DIN] = [K,64])
    gemm_fin<<<gF, blk, SMEMF_BYTES>>>(d1, wz0, HID,
        d2, wx0, HID, d3, wx1, HID, d4, wx2, HID,
        WxL, out);
}

// round 17
// speedup vs baseline: 1.7812x; 1.1926x over previous
#include <cuda_runtime.h>
#include <cuda_fp16.h>
#include <mma.h>
#include <math.h>
#include <cstdint>

using namespace nvcuda;

// Problem shapes
#define BATCH 65536
#define DIN   64
#define HID   512

// GEMM tile config (fp16 operands, fp32 accum) — proven config
#define BM 128
#define BN 128
#define BKC 64
#define LDA_H 72     // 64 + 8 pad halfs
#define LDB_H 144    // 128 + 16 pad halfs
#define NTHREADS 256
#define STAGES 3

#define A_STAGE_HALFS (BM * LDA_H)     // 9216
#define W_STAGE_HALFS 9216             // max(128*72, 64*144)
#define STAGE_HALFS  (A_STAGE_HALFS + W_STAGE_HALFS)   // 18432
#define SMEM_BYTES   (STAGES * STAGE_HALFS * 2)        // 110592 -> 2 CTAs/SM

// final-GEMM (N=64) specialization
#define LDBF_H 72
#define BF_STAGE_HALFS (64 * LDBF_H)                   // 4608
#define STAGEF_HALFS (A_STAGE_HALFS + BF_STAGE_HALFS)  // 13824
#define SMEMF_BYTES  (STAGES * STAGEF_HALFS * 2)       // 82944 -> 2 CTAs/SM

// ---------------- scratch ----------------
__device__ __align__(256) __half g_xm1[BATCH * DIN];
__device__ __align__(256) __half g_a1[BATCH * HID];
__device__ __align__(256) __half g_a2[BATCH * HID];
__device__ __align__(256) __half g_a3[BATCH * HID];
__device__ __align__(256) __half g_d1[BATCH * HID];
__device__ __align__(256) __half g_d2[BATCH * HID];
__device__ __align__(256) __half g_d3[BATCH * HID];
__device__ __align__(256) __half g_d4[BATCH * HID];
__device__ __align__(256) __half g_wz0[HID * DIN];
__device__ __align__(256) __half g_wz1[HID * HID];
__device__ __align__(256) __half g_wz2[HID * HID];
__device__ __align__(256) __half g_wz3[HID * HID];
__device__ __align__(256) __half g_wx0[HID * DIN];
__device__ __align__(256) __half g_wx1[HID * DIN];
__device__ __align__(256) __half g_wx2[HID * DIN];

// ---------------- prep kernel: x-1 conversion + ALL weight conversions ----------------
__global__ void prep_all(
    const float* __restrict__ state,
    const float* __restrict__ Wz0, const float* __restrict__ Wx0,
    const float* __restrict__ Wx1, const float* __restrict__ Wx2,
    const float* __restrict__ Wz1, const float* __restrict__ Wz2, const float* __restrict__ Wz3,
    __half* __restrict__ xm1,
    __half* __restrict__ wz0, __half* __restrict__ wx0,
    __half* __restrict__ wx1, __half* __restrict__ wx2,
    __half* __restrict__ wz1, __half* __restrict__ wz2, __half* __restrict__ wz3)
{
    const int NX = BATCH * DIN;       // 4194304
    const int S  = HID * DIN;         // 32768
    const int L  = HID * HID;         // 262144
    int i = blockIdx.x * blockDim.x + threadIdx.x;
    if (i < NX) {
        xm1[i] = __float2half_rn(state[i] - 1.0f);
        return;
    }
    int j = i - NX;
    if (j < 4 * S) {
        int seg = j / S, off = j - seg * S;
        const float* src = (seg == 0) ? Wz0 : (seg == 1) ? Wx0 : (seg == 2) ? Wx1 : Wx2;
        __half* dst      = (seg == 0) ? wz0 : (seg == 1) ? wx0 : (seg == 2) ? wx1 : wx2;
        dst[off] = __float2half_rn(src[off]);
        return;
    }
    j -= 4 * S;
    if (j < 3 * L) {
        int seg = j / L, off = j - seg * L;
        const float* src = (seg == 0) ? Wz1 : (seg == 1) ? Wz2 : Wz3;
        __half* dst      = (seg == 0) ? wz1 : (seg == 1) ? wz2 : wz3;
        dst[off] = __float2half_rn(src[off]);
    }
}

// ---------------- helpers ----------------
// softplus via fast intrinsics; guarded for large p
__device__ __forceinline__ float softplus_fast(float p) {
    return (p > 20.0f) ? p : __logf(1.0f + __expf(p));
}
// sigmoid via fast exp
__device__ __forceinline__ float sigmoid_fast(float p) {
    return 1.0f / (1.0f + __expf(-p));
}
// sigmoid recovered from softplus value a = log(1+e^p):  s = 1 - e^{-a}
__device__ __forceinline__ float gate_from_a(float a) {
    return 1.0f - __expf(-a);
}

__device__ __forceinline__ void cp_async16(__half* smem_dst, const __half* gmem_src) {
    unsigned int s = (unsigned int)__cvta_generic_to_shared(smem_dst);
    asm volatile("cp.async.cg.shared.global [%0], [%1], 16;\n"
                 :: "r"(s), "l"(gmem_src));
}
__device__ __forceinline__ void cp_commit() { asm volatile("cp.async.commit_group;\n" ::: "memory"); }
__device__ __forceinline__ void cp_wait0() { asm volatile("cp.async.wait_group 0;\n" ::: "memory"); }
__device__ __forceinline__ void cp_wait1() { asm volatile("cp.async.wait_group 1;\n" ::: "memory"); }

// Epilogue modes
#define MODE_FWD 0   // out1h = softplus(p+b)            (sigmoid recovered later)
#define MODE_L4  1   // out1h = vecn[col] * sigmoid(p+b)
#define MODE_BWD 2   // out1h = (1 - exp(-a[oi])) * p    (a = stored softplus)

__device__ __forceinline__ void get_iter(
    int it,
    const __half* A0, const __half* W0, int K0,
    const __half* A1, const __half* W1, int K1,
    const __half* A2, const __half* W2, int K2,
    const __half* A3, const __half* W3, int K3,
    const __half*& A, const __half*& W, int& K, int& k0)
{
    int n0 = K0 >> 6;
    if (it < n0) { A = A0; W = W0; K = K0; k0 = it << 6; return; }
    it -= n0;
    int n1 = K1 >> 6;
    if (it < n1) { A = A1; W = W1; K = K1; k0 = it << 6; return; }
    it -= n1;
    int n2 = K2 >> 6;
    if (it < n2) { A = A2; W = W2; K = K2; k0 = it << 6; return; }
    it -= n2;
    A = A3; W = W3; K = K3; k0 = it << 6;
}

// Stage one K-chunk: A tile [128 x 64] halfs; W tile.
// BT=true : W [N,K] row-major -> sW[n*LDA_H + k]
// BT=false: W [K,N] row-major (N==HID for all uses) -> sW[k*LDB_H + n]
template<bool BT>
__device__ __forceinline__ void stage_tiles(
    __half* sA, __half* sW,
    const __half* __restrict__ A, const __half* __restrict__ W,
    int K, int k0, int m0, int n0, int N, int tid)
{
    #pragma unroll
    for (int t = 0; t < 4; t++) {
        int slot = tid + t * NTHREADS;
        int row = slot >> 3, kq = slot & 7;
        cp_async16(&sA[row * LDA_H + (kq << 3)],
                   A + (size_t)(m0 + row) * K + k0 + (kq << 3));
    }
    if (BT) {
        #pragma unroll
        for (int t = 0; t < 4; t++) {
            int slot = tid + t * NTHREADS;
            int n = slot >> 3, kq = slot & 7;
            cp_async16(&sW[n * LDA_H + (kq << 3)],
                       W + (size_t)(n0 + n) * K + k0 + (kq << 3));
        }
    } else {
        #pragma unroll
        for (int t = 0; t < 4; t++) {
            int slot = tid + t * NTHREADS;
            int krow = slot >> 4, nq = slot & 15;
            int col = n0 + (nq << 3);
            cp_async16(&sW[krow * LDB_H + (nq << 3)],
                       W + (size_t)(k0 + krow) * N + col);
        }
    }
}

// fp16 fused GEMM, 3-stage cp.async ring, one __syncthreads per iteration.
template<bool BT, int MODE>
__global__ void __launch_bounds__(NTHREADS, 2)
gemm_h(const __half* __restrict__ A0, const __half* __restrict__ W0, int K0,
       const __half* __restrict__ A1, const __half* __restrict__ W1, int K1,
       const __half* __restrict__ A2, const __half* __restrict__ W2, int K2,
       const __half* __restrict__ A3, const __half* __restrict__ W3, int K3,
       int N,
       const float* __restrict__ bias,
       const float* __restrict__ vecn,
       const __half* __restrict__ agate,
       __half* __restrict__ out1h)
{
    extern __shared__ __half smem_h[];

    const int tid    = threadIdx.x;
    const int warpId = tid >> 5;
    const int lane   = tid & 31;
    const int wm     = warpId >> 2;   // 0..1
    const int wn     = warpId & 3;    // 0..3
    const int m0     = blockIdx.y * BM;
    const int n0     = blockIdx.x * BN;

    wmma::fragment<wmma::accumulator, 16, 16, 16, float> acc[4][2];
    #pragma unroll
    for (int i = 0; i < 4; i++)
        #pragma unroll
        for (int j = 0; j < 2; j++)
            wmma::fill_fragment(acc[i][j], 0.0f);

    const int niter = (K0 >> 6) + (K1 >> 6) + (K2 >> 6) + (K3 >> 6);

    // prologue: stage chunk 0 and 1
    #pragma unroll
    for (int j = 0; j < 2; j++) {
        if (j < niter) {
            const __half *A, *W; int K, k0;
            get_iter(j, A0,W0,K0, A1,W1,K1, A2,W2,K2, A3,W3,K3, A, W, K, k0);
            stage_tiles<BT>(smem_h + j * STAGE_HALFS,
                            smem_h + j * STAGE_HALFS + A_STAGE_HALFS,
                            A, W, K, k0, m0, n0, N, tid);
            cp_commit();
        }
    }

    for (int it = 0; it < niter; ++it) {
        if (it + 1 < niter) cp_wait1(); else cp_wait0();
        __syncthreads();

        const int nxt = it + 2;
        if (nxt < niter) {
            const __half *A, *W; int K, k0;
            get_iter(nxt, A0,W0,K0, A1,W1,K1, A2,W2,K2, A3,W3,K3, A, W, K, k0);
            __half* nb = smem_h + (nxt % STAGES) * STAGE_HALFS;
            stage_tiles<BT>(nb, nb + A_STAGE_HALFS, A, W, K, k0, m0, n0, N, tid);
            cp_commit();
        }

        __half* sA = smem_h + (it % STAGES) * STAGE_HALFS;
        __half* sW = sA + A_STAGE_HALFS;

        #pragma unroll
        for (int kk = 0; kk < BKC; kk += 16) {
            wmma::fragment<wmma::matrix_a, 16, 16, 16, __half, wmma::row_major> af[4];
            #pragma unroll
            for (int i = 0; i < 4; i++)
                wmma::load_matrix_sync(af[i], &sA[(wm * 64 + i * 16) * LDA_H + kk], LDA_H);
            if (BT) {
                wmma::fragment<wmma::matrix_b, 16, 16, 16, __half, wmma::col_major> bf[2];
                #pragma unroll
                for (int j = 0; j < 2; j++)
                    wmma::load_matrix_sync(bf[j], &sW[(wn * 32 + j * 16) * LDA_H + kk], LDA_H);
                #pragma unroll
                for (int i = 0; i < 4; i++)
                    #pragma unroll
                    for (int j = 0; j < 2; j++)
                        wmma::mma_sync(acc[i][j], af[i], bf[j], acc[i][j]);
            } else {
                wmma::fragment<wmma::matrix_b, 16, 16, 16, __half, wmma::row_major> bf[2];
                #pragma unroll
                for (int j = 0; j < 2; j++)
                    wmma::load_matrix_sync(bf[j], &sW[kk * LDB_H + wn * 32 + j * 16], LDB_H);
                #pragma unroll
                for (int i = 0; i < 4; i++)
                    #pragma unroll
                    for (int j = 0; j < 2; j++)
                        wmma::mma_sync(acc[i][j], af[i], bf[j], acc[i][j]);
            }
        }
    }

    // ---- epilogue ----
    __syncthreads();
    float* ep = reinterpret_cast<float*>(smem_h) + warpId * 288;

    #pragma unroll
    for (int i = 0; i < 4; i++) {
        #pragma unroll
        for (int j = 0; j < 2; j++) {
            const int rbase = m0 + wm * 64 + i * 16;
            const int cbase = n0 + wn * 32 + j * 16;
            wmma::store_matrix_sync(ep, acc[i][j], 16, wmma::mem_row_major);
            __syncwarp();
            #pragma unroll
            for (int e = 0; e < 8; e++) {
                int lin = e * 32 + lane;
                int r = lin >> 4;
                int c = lin & 15;
                int col = cbase + c;
                float p = ep[lin];
                size_t oi = (size_t)(rbase + r) * N + col;
                if (MODE == MODE_FWD) {
                    p += bias[col];
                    out1h[oi] = __float2half_rn(softplus_fast(p));
                } else if (MODE == MODE_L4) {
                    p += bias[col];
                    out1h[oi] = __float2half_rn(vecn[col] * sigmoid_fast(p));
                } else { // MODE_BWD: gate recovered from stored softplus
                    float a = __half2float(agate[oi]);
                    out1h[oi] = __float2half_rn(gate_from_a(a) * p);
                }
            }
            __syncwarp();
        }
    }
}

// ---------------- final GEMM: N=64 specialized (BN=64, warp tile 64x16) ----------------
__device__ __forceinline__ void stage_fin(
    __half* sA, __half* sW,
    const __half* __restrict__ A, const __half* __restrict__ W,
    int K, int k0, int m0, int tid)
{
    #pragma unroll
    for (int t = 0; t < 4; t++) {
        int slot = tid + t * NTHREADS;
        int row = slot >> 3, kq = slot & 7;
        cp_async16(&sA[row * LDA_H + (kq << 3)],
                   A + (size_t)(m0 + row) * K + k0 + (kq << 3));
    }
    // W [K,64]: 64 k-rows x 8 chunks = 512 chunks, 2/thread
    #pragma unroll
    for (int t = 0; t < 2; t++) {
        int slot = tid + t * NTHREADS;
        int krow = slot >> 3, nq = slot & 7;
        cp_async16(&sW[krow * LDBF_H + (nq << 3)],
                   W + (size_t)(k0 + krow) * DIN + (nq << 3));
    }
}

__global__ void __launch_bounds__(NTHREADS, 2)
gemm_fin(const __half* __restrict__ A0, const __half* __restrict__ W0, int K0,
         const __half* __restrict__ A1, const __half* __restrict__ W1, int K1,
         const __half* __restrict__ A2, const __half* __restrict__ W2, int K2,
         const __half* __restrict__ A3, const __half* __restrict__ W3, int K3,
         const float* __restrict__ vecn,
         float* __restrict__ out1f)
{
    extern __shared__ __half smem_h[];

    const int tid    = threadIdx.x;
    const int warpId = tid >> 5;
    const int lane   = tid & 31;
    const int wm     = warpId >> 2;   // 0..1 (64-row slab)
    const int wn     = warpId & 3;    // 0..3 (16-col slab)
    const int m0     = blockIdx.y * BM;

    wmma::fragment<wmma::accumulator, 16, 16, 16, float> acc[4];
    #pragma unroll
    for (int i = 0; i < 4; i++)
        wmma::fill_fragment(acc[i], 0.0f);

    const int niter = (K0 >> 6) + (K1 >> 6) + (K2 >> 6) + (K3 >> 6);

    #pragma unroll
    for (int j = 0; j < 2; j++) {
        if (j < niter) {
            const __half *A, *W; int K, k0;
            get_iter(j, A0,W0,K0, A1,W1,K1, A2,W2,K2, A3,W3,K3, A, W, K, k0);
            stage_fin(smem_h + j * STAGEF_HALFS,
                      smem_h + j * STAGEF_HALFS + A_STAGE_HALFS,
                      A, W, K, k0, m0, tid);
            cp_commit();
        }
    }

    for (int it = 0; it < niter; ++it) {
        if (it + 1 < niter) cp_wait1(); else cp_wait0();
        __syncthreads();

        const int nxt = it + 2;
        if (nxt < niter) {
            const __half *A, *W; int K, k0;
            get_iter(nxt, A0,W0,K0, A1,W1,K1, A2,W2,K2, A3,W3,K3, A, W, K, k0);
            __half* nb = smem_h + (nxt % STAGES) * STAGEF_HALFS;
            stage_fin(nb, nb + A_STAGE_HALFS, A, W, K, k0, m0, tid);
            cp_commit();
        }

        __half* sA = smem_h + (it % STAGES) * STAGEF_HALFS;
        __half* sW = sA + A_STAGE_HALFS;

        #pragma unroll
        for (int kk = 0; kk < BKC; kk += 16) {
            wmma::fragment<wmma::matrix_a, 16, 16, 16, __half, wmma::row_major> af[4];
            #pragma unroll
            for (int i = 0; i < 4; i++)
                wmma::load_matrix_sync(af[i], &sA[(wm * 64 + i * 16) * LDA_H + kk], LDA_H);
            wmma::fragment<wmma::matrix_b, 16, 16, 16, __half, wmma::row_major> bf;
            wmma::load_matrix_sync(bf, &sW[kk * LDBF_H + wn * 16], LDBF_H);
            #pragma unroll
            for (int i = 0; i < 4; i++)
                wmma::mma_sync(acc[i], af[i], bf, acc[i]);
        }
    }

    __syncthreads();
    float* ep = reinterpret_cast<float*>(smem_h) + warpId * 288;

    #pragma unroll
    for (int i = 0; i < 4; i++) {
        const int rbase = m0 + wm * 64 + i * 16;
        const int cbase = wn * 16;
        wmma::store_matrix_sync(ep, acc[i], 16, wmma::mem_row_major);
        __syncwarp();
        #pragma unroll
        for (int e = 0; e < 8; e++) {
            int lin = e * 32 + lane;
            int r = lin >> 4;
            int c = lin & 15;
            int col = cbase + c;
            float p = ep[lin];
            out1f[(size_t)(rbase + r) * DIN + col] = p + vecn[col];
        }
        __syncwarp();
    }
}

// ---------------- host launcher ----------------
extern "C" void kernel_launch(void* const* d_in, const int* in_sizes, int n_in,
                              void* d_out, int out_size)
{
    const float* state = (const float*)d_in[0];
    const float* Wz0   = (const float*)d_in[1];
    const float* bz0   = (const float*)d_in[2];
    const float* Wz1   = (const float*)d_in[3];
    const float* Wz2   = (const float*)d_in[4];
    const float* Wz3   = (const float*)d_in[5];
    const float* WzL   = (const float*)d_in[6];
    const float* Wx0   = (const float*)d_in[7];
    const float* bx0   = (const float*)d_in[8];
    const float* Wx1   = (const float*)d_in[9];
    const float* bx1   = (const float*)d_in[10];
    const float* Wx2   = (const float*)d_in[11];
    const float* bx2   = (const float*)d_in[12];
    const float* WxL   = (const float*)d_in[13];
    float* out = (float*)d_out;

    cudaFuncSetAttribute(gemm_h<true,  MODE_FWD>, cudaFuncAttributeMaxDynamicSharedMemorySize, SMEM_BYTES);
    cudaFuncSetAttribute(gemm_h<true,  MODE_L4>,  cudaFuncAttributeMaxDynamicSharedMemorySize, SMEM_BYTES);
    cudaFuncSetAttribute(gemm_h<false, MODE_BWD>, cudaFuncAttributeMaxDynamicSharedMemorySize, SMEM_BYTES);
    cudaFuncSetAttribute(gemm_fin, cudaFuncAttributeMaxDynamicSharedMemorySize, SMEMF_BYTES);

    void* p;
    __half *xm1, *a1, *a2, *a3, *d1, *d2, *d3, *d4;
    __half *wz0, *wz1, *wz2, *wz3, *wx0, *wx1, *wx2;
    cudaGetSymbolAddress(&p, g_xm1);  xm1  = (__half*)p;
    cudaGetSymbolAddress(&p, g_a1);   a1   = (__half*)p;
    cudaGetSymbolAddress(&p, g_a2);   a2   = (__half*)p;
    cudaGetSymbolAddress(&p, g_a3);   a3   = (__half*)p;
    cudaGetSymbolAddress(&p, g_d1);   d1   = (__half*)p;
    cudaGetSymbolAddress(&p, g_d2);   d2   = (__half*)p;
    cudaGetSymbolAddress(&p, g_d3);   d3   = (__half*)p;
    cudaGetSymbolAddress(&p, g_d4);   d4   = (__half*)p;
    cudaGetSymbolAddress(&p, g_wz0);  wz0  = (__half*)p;
    cudaGetSymbolAddress(&p, g_wz1);  wz1  = (__half*)p;
    cudaGetSymbolAddress(&p, g_wz2);  wz2  = (__half*)p;
    cudaGetSymbolAddress(&p, g_wz3);  wz3  = (__half*)p;
    cudaGetSymbolAddress(&p, g_wx0);  wx0  = (__half*)p;
    cudaGetSymbolAddress(&p, g_wx1);  wx1  = (__half*)p;
    cudaGetSymbolAddress(&p, g_wx2);  wx2  = (__half*)p;

    const int nTot = BATCH * DIN + 4 * HID * DIN + 3 * HID * HID;  // 5111808
    prep_all<<<(nTot + 255) / 256, 256>>>(state, Wz0, Wx0, Wx1, Wx2, Wz1, Wz2, Wz3,
                                          xm1, wz0, wx0, wx1, wx2, wz1, wz2, wz3);

    dim3 blk(NTHREADS);
    dim3 gH(HID / BN, BATCH / BM);   // (4, 512)
    dim3 gF(1, BATCH / BM);          // (1, 512)

    // Forward (BT=true: B = W^T, W is [N,K] row-major); store softplus only
    gemm_h<true, MODE_FWD><<<gH, blk, SMEM_BYTES>>>(xm1, wz0, DIN,
        nullptr, nullptr, 0, nullptr, nullptr, 0, nullptr, nullptr, 0,
        HID, bz0, nullptr, nullptr, a1);
    gemm_h<true, MODE_FWD><<<gH, blk, SMEM_BYTES>>>(a1, wz1, HID,
        xm1, wx0, DIN, nullptr, nullptr, 0, nullptr, nullptr, 0,
        HID, bx0, nullptr, nullptr, a2);
    gemm_h<true, MODE_FWD><<<gH, blk, SMEM_BYTES>>>(a2, wz2, HID,
        xm1, wx1, DIN, nullptr, nullptr, 0, nullptr, nullptr, 0,
        HID, bx1, nullptr, nullptr, a3);
    gemm_h<true, MODE_L4><<<gH, blk, SMEM_BYTES>>>(a3, wz3, HID,
        xm1, wx2, DIN, nullptr, nullptr, 0, nullptr, nullptr, 0,
        HID, bx2, WzL, nullptr, d4);

    // Backward: d_k = (1 - exp(-a_k)) * (d_{k+1} @ Wz_{k+1})
    gemm_h<false, MODE_BWD><<<gH, blk, SMEM_BYTES>>>(d4, wz3, HID,
        nullptr, nullptr, 0, nullptr, nullptr, 0, nullptr, nullptr, 0,
        HID, nullptr, nullptr, a3, d3);
    gemm_h<false, MODE_BWD><<<gH, blk, SMEM_BYTES>>>(d3, wz2, HID,
        nullptr, nullptr, 0, nullptr, nullptr, 0, nullptr, nullptr, 0,
        HID, nullptr, nullptr, a2, d2);
    gemm_h<false, MODE_BWD><<<gH, blk, SMEM_BYTES>>>(d2, wz1, HID,
        nullptr, nullptr, 0, nullptr, nullptr, 0, nullptr, nullptr, 0,
        HID, nullptr, nullptr, a1, d1);

    // Final: action = WxL + d1@Wz0 + d2@Wx0 + d3@Wx1 + d4@Wx2 (all [HID,DIN] = [K,64])
    gemm_fin<<<gF, blk, SMEMF_BYTES>>>(d1, wz0, HID,
        d2, wx0, HID, d3, wx1, HID, d4, wx2, HID,
        WxL, out);
}